// round 11
// baseline (speedup 1.0000x reference)
#include <cuda_runtime.h>
#include <stdint.h>

// Problem shape (fixed by reference setup_inputs)
#define BB 128
#define AA 1024
#define MM 6
#define TT 16
#define SPLIT 4                              // CTAs per batch element
#define THREADS1 256                         // kernel1 block: 8 warps x 32 agents
#define NW (THREADS1 / 32)                   // 8

#define AGENT_THRESH 0.5f
#define X_DIS_THRESH 1.5f
#define Y_DIS_THRESH 3.0f
#define DIS_THRESH_SQ 9.0f                   // dist > 3  <=>  dx*dx+dy*dy > 9
#define MEAN_SCALE (1.0f / (float)(BB * TT * 2))

// Cross-CTA min scratch. Entry (b*32 + t*2 + coord) holds ~bits(min_val).
// Zero-initialized == "+inf" sentinel (key 0 -> largest decoded value).
// Kernel2 resets entries to 0 after consuming them (graph-replay safe).
__device__ uint32_t g_minkey[BB * TT * 2];

__global__ __launch_bounds__(THREADS1, 4)
void collision_min_kernel(
    const float* __restrict__ ego_plan,   // [B, T, 2]
    const float* __restrict__ preds,      // [B, A, M, T, 2] (one traj == 128B)
    const float* __restrict__ scores)     // [B, A, M]
{
    const int split = blockIdx.x;         // 0..SPLIT-1
    const int b     = blockIdx.y;         // 0..BB-1
    const int tid   = threadIdx.x;
    const int wid   = tid >> 5;
    const int lane  = tid & 31;
    const int half  = lane >> 4;          // 0: even agents, 1: odd agents
    const int t     = lane & 15;          // timestep owned by this lane

    const int agent0 = split * (AA / SPLIT) + wid * 32;   // warp's first agent

    __shared__ float    s_scores[NW][MM * 32];  // 6 KB coalesced score staging
    __shared__ uint32_t s_off[NW][32];
    __shared__ float    s_pen[NW][32];
    __shared__ float    s_xr[NW][16];
    __shared__ float    s_yr[NW][16];

    // ---- coalesced score load: 192 contiguous floats per warp ----
    const float* sbase = scores + ((size_t)b * AA + agent0) * MM;
#pragma unroll
    for (int i = 0; i < MM; i++)
        s_scores[wid][i * 32 + lane] = __ldg(&sbase[i * 32 + lane]);
    __syncwarp();

    // ---- per-lane argmax for agent (agent0 + lane), first-max wins ----
    float best = s_scores[wid][lane * MM];
    int   bm   = 0;
#pragma unroll
    for (int m = 1; m < MM; m++) {
        float v = s_scores[wid][lane * MM + m];
        if (v > best) { best = v; bm = m; }
    }
    const uint32_t g = (uint32_t)(b * AA + agent0 + lane);
    s_off[wid][lane] = (g * MM + (uint32_t)bm) * (TT * 2 * 4);  // byte offset
    s_pen[wid][lane] = (best < AGENT_THRESH) ? 100.0f : 0.0f;
    __syncwarp();

    const float2 eg = __ldg(&((const float2*)(ego_plan + b * TT * 2))[t]);

    // ---- shuffle-free mainloop: 2 agents/iter, float2 per lane ----
    float xmin = 1e30f, ymin = 1e30f;
#pragma unroll
    for (int j = 0; j < 16; j++) {
        const int a0 = 2 * j + half;
        const uint32_t off  = s_off[wid][a0];        // broadcast LDS
        const float    penj = s_pen[wid][a0];
        const float2 v = __ldg((const float2*)((const char*)preds + off + t * 8));
        const float dx = eg.x - v.x;
        const float dy = eg.y - v.y;
        const float pen = (dx * dx + dy * dy > DIS_THRESH_SQ) ? 100.0f : penj;
        xmin = fminf(xmin, fabsf(dx) + pen);
        ymin = fminf(ymin, fabsf(dy) + pen);
    }

    // combine halves -> per-timestep min over this warp's 32 agents
    xmin = fminf(xmin, __shfl_xor_sync(0xffffffffu, xmin, 16));
    ymin = fminf(ymin, __shfl_xor_sync(0xffffffffu, ymin, 16));
    if (lane < 16) { s_xr[wid][lane] = xmin; s_yr[wid][lane] = ymin; }
    __syncthreads();

    // ---- cross-warp min (8 warps = 256 agents) + global atomic-min ----
    if (tid < 32) {
        const int  tt  = lane & 15;
        const int  isY = lane >> 4;
        float m = isY ? s_yr[0][tt] : s_xr[0][tt];
#pragma unroll
        for (int w = 1; w < NW; w++)
            m = fminf(m, isY ? s_yr[w][tt] : s_xr[w][tt]);
        // values are non-negative: max over ~bits == min over value
        atomicMax(&g_minkey[b * 32 + tt * 2 + isY], ~__float_as_uint(m));
    }
}

// Single block: consume scratch, compute loss + masked mean, reset scratch.
__global__ __launch_bounds__(1024, 1)
void finalize_kernel(const float* __restrict__ pmask,  // [B, T]
                     float* __restrict__ out)
{
    const int tid = threadIdx.x;
    __shared__ float s_part[32];

    float acc = 0.0f;
#pragma unroll
    for (int e = tid; e < BB * 32; e += 1024) {
        const uint32_t key = g_minkey[e];
        g_minkey[e] = 0u;                          // reset for next replay
        const float val = __uint_as_float(~key);
        const int b  = e >> 5;
        const int r  = e & 31;
        const int t  = r >> 1;
        const float thr  = (r & 1) ? Y_DIS_THRESH : X_DIS_THRESH;
        const float loss = (val <= thr) ? (thr - val) : 0.0f;
        acc += loss * __ldg(&pmask[b * TT + t]);
    }

#pragma unroll
    for (int o = 16; o > 0; o >>= 1)
        acc += __shfl_xor_sync(0xffffffffu, acc, o);
    if ((tid & 31) == 0) s_part[tid >> 5] = acc;
    __syncthreads();
    if (tid < 32) {
        float v = s_part[tid];
#pragma unroll
        for (int o = 16; o > 0; o >>= 1)
            v += __shfl_xor_sync(0xffffffffu, v, o);
        if (tid == 0) out[0] = v * MEAN_SCALE;
    }
}

extern "C" void kernel_launch(void* const* d_in, const int* in_sizes, int n_in,
                              void* d_out, int out_size)
{
    const float* ego_plan = (const float*)d_in[0];  // [B,T,2]
    const float* preds    = (const float*)d_in[1];  // [B,A,M,T,2]
    const float* scores   = (const float*)d_in[2];  // [B,A,M]
    const float* pmask    = (const float*)d_in[3];  // [B,T]
    float* out = (float*)d_out;

    dim3 grid1(SPLIT, BB);
    collision_min_kernel<<<grid1, THREADS1>>>(ego_plan, preds, scores);
    finalize_kernel<<<1, 1024>>>(pmask, out);
}